// round 10
// baseline (speedup 1.0000x reference)
#include <cuda_runtime.h>
#include <cuda_fp16.h>

#define NMAX 4194304
#define CN   10
#define NB2  296                       // persistent blocks, 2 per SM (co-resident)
#define T1   256
#define CHP  256                       // pairs per chunk (2 samples/thread, R5 layout)
#define CH_F4 (CHP * 5)                // 1280 float4 per tensor per chunk
#define TEN_B (CH_F4 * 16)             // 20480 B per tensor per buffer
#define BUF_B (2 * TEN_B)              // 40960 B per buffer (P+Y)
#define STG_TOTAL (2 * BUF_B)          // 81920 B (2 buffers)
#define HSTRIDE 45                     // half2 hist words per thread
#define HIST_BYTES (T1 * HSTRIDE * 4)  // 46080 <= STG_TOTAL (union)
#define SMEM_TOTAL STG_TOTAL           // 81920 -> 2 blocks/SM

// ---------------- device globals --------------------------------------------
struct GAcc {
    double   ce, fo;
    unsigned umaxb, uminneg;   // max(unc bits), max(~unc bits) (zero-init neutral)
    unsigned arrive, ticket;
    float    histF[88];        // [(b*2+acc)*2 + {0:wc,1:wu}], b in [0,21]
};
static __device__ GAcc g;      // zero at load; finalizer self-resets
static __device__ __align__(16) float g_rec[NMAX];   // unc, sign bit = !acc

// ---------------- fast math (FFMA-only, no MUFU) ----------------------------
__device__ __forceinline__ float fast_logf(float a) {
    int   e = (__float_as_int(a) - 0x3f2aaaab) & 0xff800000;
    float m = __int_as_float(__float_as_int(a) - e);
    float i = (float)e * 1.19209290e-7f;
    float f = m - 1.0f;
    float s = f * f;
    float r = fmaf(0.230836749f, f, -0.279208571f);
    float t = fmaf(0.331826031f, f, -0.498910338f);
    r = fmaf(r, s, t);
    r = fmaf(r, s, f);
    r = fmaf(i, 0.693147182f, r);
    return r;
}
__device__ __forceinline__ float fast_expf(float a) {
    float j  = fmaf(1.442695041f, a, 12582912.0f);
    int   ji = __float_as_int(j) - 0x4B400000;
    j = j - 12582912.0f;
    float f = fmaf(j, -0.693145752f, a);
    f = fmaf(j, -1.42860677e-6f, f);
    float r = 1.37805939e-3f;
    r = fmaf(r, f, 8.37312452e-3f);
    r = fmaf(r, f, 4.16695364e-2f);
    r = fmaf(r, f, 1.66665524e-1f);
    r = fmaf(r, f, 4.99999851e-1f);
    r = fmaf(r, f, 1.00000000e+0f);
    r = fmaf(r, f, 1.00000000e+0f);
    return __int_as_float(__float_as_int(r) + (ji << 23));
}
__device__ __forceinline__ float fast_rcp(float x) {   // x in (1,2]: FFMA Newton
    float r = __int_as_float(0x7EF311C3 - __float_as_int(x));
    r = r * fmaf(-x, r, 2.0f);
    r = r * fmaf(-x, r, 2.0f);
    r = r * fmaf(-x, r, 2.0f);
    return r;
}

// ---------------- cp.async / cache-policy helpers ---------------------------
__device__ __forceinline__ unsigned long long pol_first() {
    unsigned long long p;
    asm("createpolicy.fractional.L2::evict_first.b64 %0, 1.0;" : "=l"(p));
    return p;
}
__device__ __forceinline__ unsigned long long pol_last() {
    unsigned long long p;
    asm("createpolicy.fractional.L2::evict_last.b64 %0, 1.0;" : "=l"(p));
    return p;
}
__device__ __forceinline__ void cp16p(unsigned dst, const void* src, unsigned long long pol) {
    asm volatile("cp.async.cg.shared.global.L2::cache_hint [%0], [%1], 16, %2;"
                 :: "r"(dst), "l"(src), "l"(pol));
}
__device__ __forceinline__ void st2_last(void* p, float a, float b, unsigned long long pol) {
    asm volatile("st.global.L2::cache_hint.v2.f32 [%0], {%1,%2}, %3;"
                 :: "l"(p), "f"(a), "f"(b), "l"(pol) : "memory");
}
__device__ __forceinline__ void cp_commit() { asm volatile("cp.async.commit_group;"); }
__device__ __forceinline__ void cp_wait1()  { asm volatile("cp.async.wait_group 1;"); }
__device__ __forceinline__ void cp_wait0()  { asm volatile("cp.async.wait_group 0;"); }

// ---------------- per-sample phase A ----------------------------------------
__device__ __forceinline__ float proc_lean(const float* p, const float* yy, int label,
                                           float& ceS, float& foS, float& umn, float& umx) {
    float ent = 0.0f, A = 0.0f, B = 0.0f;
    float best = p[0]; int arg = 0;
    #pragma unroll
    for (int c = 0; c < CN; c++) {
        float pk  = p[c];
        float lpe = fast_logf(fmaxf(pk, 1e-10f));             // EPS clamp (entropy)
        float lpf = (pk >= 1e-8f) ? lpe : -18.420680744f;     // FOCAL_EPS clamp
        ent = fmaf(pk, lpe, ent);
        float yl = yy[c] * lpf;
        A += yl;
        B = fmaf(yl, pk, B);
        if (c > 0 && pk > best) { best = pk; arg = c; }       // first-occurrence argmax
    }
    float unc = fmaxf(-ent, 0.0f);
    ceS += -A;
    foS += (B - A);
    umn = fminf(umn, unc);
    umx = fmaxf(umx, unc);
    int acc = (arg == label);
    return __int_as_float(__float_as_int(unc) | (acc ? 0 : 0x80000000));
}

// ---------------- phase B: bin one record into per-thread half2 hist --------
__device__ __forceinline__ void hist_one(unsigned* base, float ux,
                                         float umin, float range, float istep, float noff) {
    int   bits = __float_as_int(ux);
    int   acc  = (bits < 0) ? 0 : 1;
    float unc  = fabsf(ux);

    // arithmetic bin + 3 exact-compare fixup (== 21-compare loop exactly)
    float u  = fmaf(unc, istep, noff);
    float kf = fminf(fmaxf(floorf(u), 1.0f), 19.0f);
    int   k  = (int)kf;
    float s5  = 0.05f * range;
    float thm = fmaf(kf - 1.0f, s5, umin);
    float th0 = fmaf(kf,        s5, umin);
    float thp = fmaf(kf + 1.0f, s5, umin);
    int b = (k - 1) + (unc > thm) + (unc > th0) + (unc > thp);   // in [0,21]

    // weights (FFMA-only)
    float e   = unc * 0.43429448190325176f;                  // unc / ln(10)
    float num = e * 0.9f;
    float den = fmaxf((1.0f - e) * 0.1f, 1e-10f);
    float s;
    if (num >= 1.18546522f * den) {            // x >= 17  -> sigmoid rounds to 1.0f
        s = 1.0f;
    } else if (num <= 0.77880078f * den) {     // x <= -25 -> contribution < 1.4e-11
        s = 0.0f;
    } else {
        float x = 100.0f * (fast_logf(fmaxf(num, 1e-37f)) - fast_logf(den));
        s = __fdividef(1.0f, 1.0f + fast_expf(-x));          // rare path
    }
    float em = fast_expf(-2.0f * unc);
    float t  = (1.0f - em) * fast_rcp(1.0f + em);             // tanh(unc), no MUFU

    float wc = (1.0f - s) * (1.0f - t);
    float wu = s * t;
    unsigned idx = (unsigned)(b * 2 + acc);
    unsigned old = base[idx];
    __half2 h  = *reinterpret_cast<__half2*>(&old);
    __half2 w  = __floats2half2_rn(wc, wu);
    h = __hadd2(h, w);
    base[idx] = *reinterpret_cast<unsigned*>(&h);
}

// ---------------- fused persistent kernel -----------------------------------
extern __shared__ __align__(16) char smem[];
// [0, 81920): phase A double-buffer staging / phase B half2 hist (46080)

__global__ void __launch_bounds__(T1) fused(const float* __restrict__ in0,
                                            const float* __restrict__ in1,
                                            int n, float* __restrict__ out) {
    __shared__ int s_label, s_swap;
    __shared__ float rC[T1/32], rF[T1/32], rMn[T1/32], rMx[T1/32];
    __shared__ float s_umin, s_umax;

    float4*   stg = reinterpret_cast<float4*>(smem);
    unsigned* hst = reinterpret_cast<unsigned*>(smem);
    const int t = threadIdx.x;

    if (t == 0) {
        bool onehot = true;
        #pragma unroll
        for (int c = 0; c < CN; c++) { float v = in1[c]; if (v != 0.0f && v != 1.0f) onehot = false; }
        const float* Y = onehot ? in1 : in0;
        s_swap = onehot ? 0 : 1;
        float best = Y[0]; int arg = 0;
        #pragma unroll
        for (int c = 1; c < CN; c++) { float v = Y[c]; if (v > best) { best = v; arg = c; } }
        s_label = arg;
    }
    __syncthreads();
    const int swap  = s_swap;
    const int label = s_label;
    const float4* P4 = reinterpret_cast<const float4*>(swap ? in1 : in0);
    const float4* Y4 = reinterpret_cast<const float4*>(swap ? in0 : in1);

    const unsigned long long pfirst = pol_first();
    const unsigned long long plast  = pol_last();

    const int npair = n >> 1;
    const int nF4   = npair * 5;
    const int ppb   = (npair + NB2 - 1) / NB2;      // pairs per block
    const int p0    = blockIdx.x * ppb;
    const int pE    = min(npair, p0 + ppb);
    const int nlp   = max(0, pE - p0);
    const int nchunk = (nlp + CHP - 1) / CHP;

    unsigned sbase = (unsigned)__cvta_generic_to_shared(stg);

    float ceS = 0.0f, foS = 0.0f;
    float umn = 3.402823466e38f, umx = 0.0f;
    float tailrec = 0.0f; int have_tail = 0;

    // ---------------- phase A: all-thread cp.async double buffer -----------
    if (nchunk > 0) {
        int gb = p0 * 5;
        #pragma unroll
        for (int r = 0; r < 5; r++) {
            int i = r * T1 + t;
            int gi = gb + i;
            if (gi < nF4) {
                cp16p(sbase + i * 16, P4 + gi, pfirst);
                cp16p(sbase + TEN_B + i * 16, Y4 + gi, pfirst);
            }
        }
    }
    cp_commit();

    int cur = 0;
    #pragma unroll 1
    for (int c = 0; c < nchunk; c++) {
        int has_next = (c + 1 < nchunk);
        if (has_next) {
            unsigned dst = sbase + (cur ^ 1) * BUF_B;
            int gb = (p0 + (c + 1) * CHP) * 5;
            #pragma unroll
            for (int r = 0; r < 5; r++) {
                int i = r * T1 + t;
                int gi = gb + i;
                if (gi < nF4) {
                    cp16p(dst + i * 16, P4 + gi, pfirst);
                    cp16p(dst + TEN_B + i * 16, Y4 + gi, pfirst);
                }
            }
        }
        cp_commit();
        if (has_next) cp_wait1(); else cp_wait0();
        __syncthreads();

        int pr = p0 + c * CHP + t;
        if (pr < pE) {
            const float4* bP = stg + cur * (BUF_B / 16);
            const float4* bY = bP + CH_F4;
            float p[20], y[20];
            #pragma unroll
            for (int j = 0; j < 5; j++) {
                float4 a = bP[t * 5 + j];
                float4 b = bY[t * 5 + j];
                p[4*j] = a.x; p[4*j+1] = a.y; p[4*j+2] = a.z; p[4*j+3] = a.w;
                y[4*j] = b.x; y[4*j+1] = b.y; y[4*j+2] = b.z; y[4*j+3] = b.w;
            }
            float r0 = proc_lean(p,      y,      label, ceS, foS, umn, umx);
            float r1 = proc_lean(p + 10, y + 10, label, ceS, foS, umn, umx);
            st2_last(g_rec + (size_t)pr * 2, r0, r1, plast);   // keep in L2
        }
        __syncthreads();
        cur ^= 1;
    }

    // odd-n tail: direct global loads, record kept in register
    if ((n & 1) && blockIdx.x == 0 && t == 0) {
        int i = n - 1;
        const float* P = swap ? in1 : in0;
        const float* Y = swap ? in0 : in1;
        float v[CN], w[CN];
        #pragma unroll
        for (int c = 0; c < CN; c++) { v[c] = P[(size_t)i * CN + c]; w[c] = Y[(size_t)i * CN + c]; }
        tailrec = proc_lean(v, w, label, ceS, foS, umn, umx);
        have_tail = 1;
    }

    // block-level reduce -> global atomics (must precede the grid barrier)
    #pragma unroll
    for (int o = 16; o; o >>= 1) {
        ceS += __shfl_xor_sync(0xffffffffu, ceS, o);
        foS += __shfl_xor_sync(0xffffffffu, foS, o);
        umn = fminf(umn, __shfl_xor_sync(0xffffffffu, umn, o));
        umx = fmaxf(umx, __shfl_xor_sync(0xffffffffu, umx, o));
    }
    int wid = t >> 5, lid = t & 31;
    if (lid == 0) { rC[wid] = ceS; rF[wid] = foS; rMn[wid] = umn; rMx[wid] = umx; }
    __syncthreads();
    if (t == 0) {
        float cc = rC[0], f = rF[0], mn = rMn[0], mx = rMx[0];
        #pragma unroll
        for (int q = 1; q < T1/32; q++) {
            cc += rC[q]; f += rF[q]; mn = fminf(mn, rMn[q]); mx = fmaxf(mx, rMx[q]);
        }
        atomicAdd(&g.ce, (double)cc);
        atomicAdd(&g.fo, (double)f);
        atomicMax(&g.umaxb, __float_as_uint(mx));
        atomicMax(&g.uminneg, ~__float_as_uint(mn));
    }

    // ---------------- grid barrier (all NB2 blocks resident) ----------------
    __threadfence();
    __syncthreads();
    if (t == 0) {
        atomicAdd(&g.arrive, 1u);
        unsigned v;
        do {
            asm volatile("ld.acquire.gpu.global.u32 %0, [%1];" : "=r"(v) : "l"(&g.arrive));
            if (v < NB2) __nanosleep(64);
        } while (v < NB2);
        s_umin = __uint_as_float(~g.uminneg);
        s_umax = __uint_as_float(g.umaxb);
    }
    __syncthreads();

    // ---------------- phase B: own slice from L2, half2 smem hist -----------
    unsigned* base = hst + t * HSTRIDE;
    #pragma unroll
    for (int k = 0; k < HSTRIDE; k++) base[k] = 0u;
    __syncthreads();

    const float umin  = s_umin;
    const float umax  = s_umax;
    const float range = umax - umin;
    const float istep = (range > 0.0f) ? __fdividef(20.0f, range) : 0.0f;
    const float noff  = -umin * istep;

    const float2* r2 = reinterpret_cast<const float2*>(g_rec) + p0;
    int i = t;
    #pragma unroll 1
    for (; i + 3 * T1 < nlp; i += 4 * T1) {          // MLP=4
        float2 a = r2[i];
        float2 b = r2[i + T1];
        float2 c = r2[i + 2 * T1];
        float2 d = r2[i + 3 * T1];
        hist_one(base, a.x, umin, range, istep, noff);
        hist_one(base, a.y, umin, range, istep, noff);
        hist_one(base, b.x, umin, range, istep, noff);
        hist_one(base, b.y, umin, range, istep, noff);
        hist_one(base, c.x, umin, range, istep, noff);
        hist_one(base, c.y, umin, range, istep, noff);
        hist_one(base, d.x, umin, range, istep, noff);
        hist_one(base, d.y, umin, range, istep, noff);
    }
    #pragma unroll 1
    for (; i < nlp; i += T1) {
        float2 a = r2[i];
        hist_one(base, a.x, umin, range, istep, noff);
        hist_one(base, a.y, umin, range, istep, noff);
    }
    if (have_tail) hist_one(base, tailrec, umin, range, istep, noff);
    __syncthreads();

    if (t < 44) {
        float swc = 0.0f, swu = 0.0f;
        #pragma unroll 8
        for (int tt = 0; tt < T1; tt++) {
            unsigned v = hst[tt * HSTRIDE + t];
            __half2 h = *reinterpret_cast<__half2*>(&v);
            swc += __low2float(h);
            swu += __high2float(h);
        }
        if (swc != 0.0f) atomicAdd(&g.histF[t * 2 + 0], swc);   // RED.F32
        if (swu != 0.0f) atomicAdd(&g.histF[t * 2 + 1], swu);
    }
    __threadfence();
    __syncthreads();

    // ---------------- finalize (last block) ----------------
    if (t == 0) {
        unsigned tk = atomicAdd(&g.ticket, 1u);
        if (tk == NB2 - 1) {
            __threadfence();
            float h[88];
            #pragma unroll 4
            for (int i2 = 0; i2 < 88; i2++) h[i2] = g.histF[i2];
            float totAU = 0.0f, totIU = 0.0f;
            #pragma unroll
            for (int b = 0; b < 22; b++) { totAU += h[4*b+3]; totIU += h[4*b+1]; }
            float pAC = 0.0f, pIC = 0.0f, pAU = 0.0f, pIU = 0.0f;
            float auc = 0.0f, prev = 0.0f, prev_tl = 0.0f;
            #pragma unroll 1
            for (int j = 0; j < 21; j++) {
                pAC += h[4*j+2];
                pIC += h[4*j+0];
                pAU += h[4*j+3];
                pIU += h[4*j+1];
                float nau = totAU - pAU, niu = totIU - pIU;
                float avu = (pAC + niu) / (pAC + nau + pIC + niu + 1e-10f);
                float tl  = (j == 20) ? 1.0f : 0.05f * (float)j;
                if (j > 0) auc += (avu + prev) * 0.5f * (tl - prev_tl);
                prev = avu; prev_tl = tl;
            }
            double dn = 1.0 / (double)n;
            out[0] = -logf(fmaxf(auc, 1e-10f)) + (float)(g.fo * dn);
            out[1] = (float)(g.ce * dn);
            // self-reset for next graph replay
            g.ce = 0.0; g.fo = 0.0;
            g.umaxb = 0u; g.uminneg = 0u;
            #pragma unroll 4
            for (int i2 = 0; i2 < 88; i2++) g.histF[i2] = 0.0f;
            g.arrive = 0u;
            __threadfence();
            g.ticket = 0u;
        }
    }
}

// ---------------- launcher --------------------------------------------------
extern "C" void kernel_launch(void* const* d_in, const int* in_sizes, int n_in,
                              void* d_out, int out_size) {
    const float* in0 = (const float*)d_in[0];
    const float* in1 = (const float*)d_in[1];
    int n = in_sizes[0] / CN;
    if (n > NMAX) n = NMAX;

    cudaFuncSetAttribute(fused, cudaFuncAttributeMaxDynamicSharedMemorySize, SMEM_TOTAL);
    fused<<<NB2, T1, SMEM_TOTAL>>>(in0, in1, n, (float*)d_out);
}

// round 12
// speedup vs baseline: 1.2123x; 1.2123x over previous
#include <cuda_runtime.h>
#include <cuda_fp16.h>

#define NMAX 4194304
#define CN   10
#define NB2  296                       // persistent blocks, 2 per SM (co-resident)
#define T1   256
#define CHP  256                       // pairs per phase-A chunk (2 samples/thread)
#define CH_F4 (CHP * 5)                // 1280 float4 per tensor per chunk
#define TEN_B (CH_F4 * 16)             // 20480 B per tensor per buffer
#define BUF_B (2 * TEN_B)              // 40960 B per buffer (P+Y)
#define STG_TOTAL (2 * BUF_B)          // 81920 B
#define HSTRIDE 45                     // half2 hist words per thread
#define SMEM_TOTAL STG_TOTAL           // 81920 -> 2 blocks/SM

// ---------------- device globals --------------------------------------------
struct GAcc {
    double   ce, fo;
    unsigned umaxb, uminneg;   // max(unc bits), max(~unc bits) (zero-init neutral)
    unsigned arrive, ticket;
    unsigned workA, pad2;      // phase-A dynamic chunk counter
    float    histF[88];        // [(b*2+acc)*2 + {0:wc,1:wu}], b in [0,21]
};
static __device__ GAcc g;      // zero at load; finalizer self-resets
static __device__ __align__(16) float g_rec[NMAX];   // unc, sign bit = !acc

// ---------------- fast math (FFMA-only, no MUFU) ----------------------------
__device__ __forceinline__ float fast_logf(float a) {
    int   e = (__float_as_int(a) - 0x3f2aaaab) & 0xff800000;
    float m = __int_as_float(__float_as_int(a) - e);
    float i = (float)e * 1.19209290e-7f;
    float f = m - 1.0f;
    float s = f * f;
    float r = fmaf(0.230836749f, f, -0.279208571f);
    float t = fmaf(0.331826031f, f, -0.498910338f);
    r = fmaf(r, s, t);
    r = fmaf(r, s, f);
    r = fmaf(i, 0.693147182f, r);
    return r;
}
__device__ __forceinline__ float fast_expf(float a) {
    float j  = fmaf(1.442695041f, a, 12582912.0f);
    int   ji = __float_as_int(j) - 0x4B400000;
    j = j - 12582912.0f;
    float f = fmaf(j, -0.693145752f, a);
    f = fmaf(j, -1.42860677e-6f, f);
    float r = 1.37805939e-3f;
    r = fmaf(r, f, 8.37312452e-3f);
    r = fmaf(r, f, 4.16695364e-2f);
    r = fmaf(r, f, 1.66665524e-1f);
    r = fmaf(r, f, 4.99999851e-1f);
    r = fmaf(r, f, 1.00000000e+0f);
    r = fmaf(r, f, 1.00000000e+0f);
    return __int_as_float(__float_as_int(r) + (ji << 23));
}
__device__ __forceinline__ float fast_rcp(float x) {   // x in (1,2]: FFMA Newton
    float r = __int_as_float(0x7EF311C3 - __float_as_int(x));
    r = r * fmaf(-x, r, 2.0f);
    r = r * fmaf(-x, r, 2.0f);
    r = r * fmaf(-x, r, 2.0f);
    return r;
}

// ---------------- cp.async / cache-policy helpers ---------------------------
__device__ __forceinline__ unsigned long long pol_first() {
    unsigned long long p;
    asm("createpolicy.fractional.L2::evict_first.b64 %0, 1.0;" : "=l"(p));
    return p;
}
__device__ __forceinline__ unsigned long long pol_last() {
    unsigned long long p;
    asm("createpolicy.fractional.L2::evict_last.b64 %0, 1.0;" : "=l"(p));
    return p;
}
__device__ __forceinline__ void cp16p(unsigned dst, const void* src, unsigned long long pol) {
    asm volatile("cp.async.cg.shared.global.L2::cache_hint [%0], [%1], 16, %2;"
                 :: "r"(dst), "l"(src), "l"(pol));
}
__device__ __forceinline__ void st2_last(void* p, float a, float b, unsigned long long pol) {
    asm volatile("st.global.L2::cache_hint.v2.f32 [%0], {%1,%2}, %3;"
                 :: "l"(p), "f"(a), "f"(b), "l"(pol) : "memory");
}
__device__ __forceinline__ void cp_commit() { asm volatile("cp.async.commit_group;"); }
__device__ __forceinline__ void cp_wait1()  { asm volatile("cp.async.wait_group 1;"); }

// ---------------- per-sample phase A ----------------------------------------
__device__ __forceinline__ float proc_lean(const float* p, const float* yy, int label,
                                           float& ceS, float& foS, float& umn, float& umx) {
    float ent = 0.0f, A = 0.0f, B = 0.0f;
    float best = p[0]; int arg = 0;
    #pragma unroll
    for (int c = 0; c < CN; c++) {
        float pk  = p[c];
        float lpe = fast_logf(fmaxf(pk, 1e-10f));             // EPS clamp (entropy)
        float lpf = (pk >= 1e-8f) ? lpe : -18.420680744f;     // FOCAL_EPS clamp
        ent = fmaf(pk, lpe, ent);
        float yl = yy[c] * lpf;
        A += yl;
        B = fmaf(yl, pk, B);
        if (c > 0 && pk > best) { best = pk; arg = c; }       // first-occurrence argmax
    }
    float unc = fmaxf(-ent, 0.0f);
    ceS += -A;
    foS += (B - A);
    umn = fminf(umn, unc);
    umx = fmaxf(umx, unc);
    int acc = (arg == label);
    return __int_as_float(__float_as_int(unc) | (acc ? 0 : 0x80000000));
}

// ---------------- phase B: bin one record into per-thread half2 hist --------
__device__ __forceinline__ void hist_one(unsigned* base, float ux,
                                         float umin, float range, float istep, float noff) {
    int   bits = __float_as_int(ux);
    int   acc  = (bits < 0) ? 0 : 1;
    float unc  = fabsf(ux);

    // arithmetic bin + 3 exact-compare fixup (== 21-compare loop exactly)
    float u  = fmaf(unc, istep, noff);
    float kf = fminf(fmaxf(floorf(u), 1.0f), 19.0f);
    int   k  = (int)kf;
    float s5  = 0.05f * range;
    float thm = fmaf(kf - 1.0f, s5, umin);
    float th0 = fmaf(kf,        s5, umin);
    float thp = fmaf(kf + 1.0f, s5, umin);
    int b = (k - 1) + (unc > thm) + (unc > th0) + (unc > thp);   // in [0,21]

    // weights (FFMA-only)
    float e   = unc * 0.43429448190325176f;                  // unc / ln(10)
    float num = e * 0.9f;
    float den = fmaxf((1.0f - e) * 0.1f, 1e-10f);
    float s;
    if (num >= 1.18546522f * den) {            // x >= 17  -> sigmoid rounds to 1.0f
        s = 1.0f;
    } else if (num <= 0.77880078f * den) {     // x <= -25 -> contribution < 1.4e-11
        s = 0.0f;
    } else {
        float x = 100.0f * (fast_logf(fmaxf(num, 1e-37f)) - fast_logf(den));
        s = __fdividef(1.0f, 1.0f + fast_expf(-x));          // rare path
    }
    float em = fast_expf(-2.0f * unc);
    float t  = (1.0f - em) * fast_rcp(1.0f + em);             // tanh(unc), no MUFU

    float wc = (1.0f - s) * (1.0f - t);
    float wu = s * t;
    unsigned idx = (unsigned)(b * 2 + acc);
    unsigned old = base[idx];
    __half2 h  = *reinterpret_cast<__half2*>(&old);
    __half2 w  = __floats2half2_rn(wc, wu);
    h = __hadd2(h, w);
    base[idx] = *reinterpret_cast<unsigned*>(&h);
}

// ---------------- fused persistent kernel -----------------------------------
extern __shared__ __align__(16) char smem[];
// [0, 81920): phase A double-buffer staging / phase B half2 hist (46080)

__global__ void __launch_bounds__(T1) fused(const float* __restrict__ in0,
                                            const float* __restrict__ in1,
                                            int n, float* __restrict__ out) {
    __shared__ int s_label, s_swap;
    __shared__ int s_chunk[2];
    __shared__ float rC[T1/32], rF[T1/32], rMn[T1/32], rMx[T1/32];
    __shared__ float s_umin, s_umax;

    float4*   stg = reinterpret_cast<float4*>(smem);
    unsigned* hst = reinterpret_cast<unsigned*>(smem);
    const int t = threadIdx.x;

    if (t == 0) {
        bool onehot = true;
        #pragma unroll
        for (int c = 0; c < CN; c++) { float v = in1[c]; if (v != 0.0f && v != 1.0f) onehot = false; }
        const float* Y = onehot ? in1 : in0;
        s_swap = onehot ? 0 : 1;
        float best = Y[0]; int arg = 0;
        #pragma unroll
        for (int c = 1; c < CN; c++) { float v = Y[c]; if (v > best) { best = v; arg = c; } }
        s_label = arg;
    }
    __syncthreads();
    const int swap  = s_swap;
    const int label = s_label;
    const float4* P4 = reinterpret_cast<const float4*>(swap ? in1 : in0);
    const float4* Y4 = reinterpret_cast<const float4*>(swap ? in0 : in1);

    const unsigned long long pfirst = pol_first();
    const unsigned long long plast  = pol_last();

    const int npair  = n >> 1;
    const int nF4    = npair * 5;
    const int nchunk = (npair + CHP - 1) / CHP;
    // static partition (used by phase B only)
    const int ppb = (npair + NB2 - 1) / NB2;
    const int p0  = blockIdx.x * ppb;
    const int pE  = min(npair, p0 + ppb);
    const int nlp = max(0, pE - p0);

    unsigned sbase = (unsigned)__cvta_generic_to_shared(stg);

    float ceS = 0.0f, foS = 0.0f;
    float umn = 3.402823466e38f, umx = 0.0f;
    float tailrec = 0.0f; int have_tail = 0;

    // ---------------- phase A: stolen chunks, double buffer -----------------
    if (t == 0) {
        s_chunk[0] = (int)atomicAdd(&g.workA, 1u);
        s_chunk[1] = (int)atomicAdd(&g.workA, 1u);
    }
    __syncthreads();
    int ca = s_chunk[0], cb = s_chunk[1];

    // prologue: always commit 2 groups (possibly empty)
    if (ca < nchunk) {
        int gb = ca * CH_F4;
        #pragma unroll
        for (int r = 0; r < 5; r++) {
            int i = r * T1 + t;
            int gi = gb + i;
            if (gi < nF4) {
                cp16p(sbase + i * 16, P4 + gi, pfirst);
                cp16p(sbase + TEN_B + i * 16, Y4 + gi, pfirst);
            }
        }
    }
    cp_commit();
    if (cb < nchunk) {
        int gb = cb * CH_F4;
        #pragma unroll
        for (int r = 0; r < 5; r++) {
            int i = r * T1 + t;
            int gi = gb + i;
            if (gi < nF4) {
                cp16p(sbase + BUF_B + i * 16, P4 + gi, pfirst);
                cp16p(sbase + BUF_B + TEN_B + i * 16, Y4 + gi, pfirst);
            }
        }
    }
    cp_commit();

    // invariant at loop top: 2 groups pending; the OLDER one is chunk ca's.
    int cur = 0;
    #pragma unroll 1
    while (ca < nchunk) {
        cp_wait1();                  // older group (ca) complete
        __syncthreads();

        int pr = ca * CHP + t;
        if (pr < npair) {
            const float4* bP = stg + cur * (BUF_B / 16);
            const float4* bY = bP + CH_F4;
            float p[20], y[20];
            #pragma unroll
            for (int j = 0; j < 5; j++) {
                float4 a = bP[t * 5 + j];
                float4 b = bY[t * 5 + j];
                p[4*j] = a.x; p[4*j+1] = a.y; p[4*j+2] = a.z; p[4*j+3] = a.w;
                y[4*j] = b.x; y[4*j+1] = b.y; y[4*j+2] = b.z; y[4*j+3] = b.w;
            }
            float r0 = proc_lean(p,      y,      label, ceS, foS, umn, umx);
            float r1 = proc_lean(p + 10, y + 10, label, ceS, foS, umn, umx);
            st2_last(g_rec + (size_t)pr * 2, r0, r1, plast);   // keep in L2
        }

        if (t == 0) s_chunk[cur] = (int)atomicAdd(&g.workA, 1u);  // monotone: safe
        __syncthreads();              // compute done + s_chunk visible
        int cc = s_chunk[cur];
        if (cc < nchunk) {
            unsigned dst = sbase + cur * BUF_B;
            int gb = cc * CH_F4;
            #pragma unroll
            for (int r = 0; r < 5; r++) {
                int i = r * T1 + t;
                int gi = gb + i;
                if (gi < nF4) {
                    cp16p(dst + i * 16, P4 + gi, pfirst);
                    cp16p(dst + TEN_B + i * 16, Y4 + gi, pfirst);
                }
            }
        }
        cp_commit();                  // restore 2-pending invariant

        ca = cb; cb = cc; cur ^= 1;
    }

    // odd-n tail: direct global loads, record kept in register
    if ((n & 1) && blockIdx.x == 0 && t == 0) {
        int i = n - 1;
        const float* P = swap ? in1 : in0;
        const float* Y = swap ? in0 : in1;
        float v[CN], w[CN];
        #pragma unroll
        for (int c = 0; c < CN; c++) { v[c] = P[(size_t)i * CN + c]; w[c] = Y[(size_t)i * CN + c]; }
        tailrec = proc_lean(v, w, label, ceS, foS, umn, umx);
        have_tail = 1;
    }

    // block-level reduce -> global atomics (must precede the grid barrier)
    #pragma unroll
    for (int o = 16; o; o >>= 1) {
        ceS += __shfl_xor_sync(0xffffffffu, ceS, o);
        foS += __shfl_xor_sync(0xffffffffu, foS, o);
        umn = fminf(umn, __shfl_xor_sync(0xffffffffu, umn, o));
        umx = fmaxf(umx, __shfl_xor_sync(0xffffffffu, umx, o));
    }
    int wid = t >> 5, lid = t & 31;
    if (lid == 0) { rC[wid] = ceS; rF[wid] = foS; rMn[wid] = umn; rMx[wid] = umx; }
    __syncthreads();
    if (t == 0) {
        float cc = rC[0], f = rF[0], mn = rMn[0], mx = rMx[0];
        #pragma unroll
        for (int q = 1; q < T1/32; q++) {
            cc += rC[q]; f += rF[q]; mn = fminf(mn, rMn[q]); mx = fmaxf(mx, rMx[q]);
        }
        atomicAdd(&g.ce, (double)cc);
        atomicAdd(&g.fo, (double)f);
        atomicMax(&g.umaxb, __float_as_uint(mx));
        atomicMax(&g.uminneg, ~__float_as_uint(mn));
    }

    // ---------------- grid barrier (all NB2 blocks resident) ----------------
    __threadfence();
    __syncthreads();
    if (t == 0) {
        atomicAdd(&g.arrive, 1u);
        unsigned v;
        do {
            asm volatile("ld.acquire.gpu.global.u32 %0, [%1];" : "=r"(v) : "l"(&g.arrive));
            if (v < NB2) __nanosleep(64);
        } while (v < NB2);
        s_umin = __uint_as_float(~g.uminneg);
        s_umax = __uint_as_float(g.umaxb);
    }
    __syncthreads();

    // ---------------- phase B: static slice from L2, half2 smem hist --------
    unsigned* base = hst + t * HSTRIDE;
    #pragma unroll
    for (int k = 0; k < HSTRIDE; k++) base[k] = 0u;
    __syncthreads();

    const float umin  = s_umin;
    const float umax  = s_umax;
    const float range = umax - umin;
    const float istep = (range > 0.0f) ? __fdividef(20.0f, range) : 0.0f;
    const float noff  = -umin * istep;

    const float2* r2 = reinterpret_cast<const float2*>(g_rec) + p0;
    int i = t;
    #pragma unroll 1
    for (; i + 3 * T1 < nlp; i += 4 * T1) {          // MLP=4
        float2 a = r2[i];
        float2 b = r2[i + T1];
        float2 c = r2[i + 2 * T1];
        float2 d = r2[i + 3 * T1];
        hist_one(base, a.x, umin, range, istep, noff);
        hist_one(base, a.y, umin, range, istep, noff);
        hist_one(base, b.x, umin, range, istep, noff);
        hist_one(base, b.y, umin, range, istep, noff);
        hist_one(base, c.x, umin, range, istep, noff);
        hist_one(base, c.y, umin, range, istep, noff);
        hist_one(base, d.x, umin, range, istep, noff);
        hist_one(base, d.y, umin, range, istep, noff);
    }
    #pragma unroll 1
    for (; i < nlp; i += T1) {
        float2 a = r2[i];
        hist_one(base, a.x, umin, range, istep, noff);
        hist_one(base, a.y, umin, range, istep, noff);
    }
    if (have_tail) hist_one(base, tailrec, umin, range, istep, noff);
    __syncthreads();

    if (t < 44) {
        float swc = 0.0f, swu = 0.0f;
        #pragma unroll 8
        for (int tt = 0; tt < T1; tt++) {
            unsigned v = hst[tt * HSTRIDE + t];
            __half2 h = *reinterpret_cast<__half2*>(&v);
            swc += __low2float(h);
            swu += __high2float(h);
        }
        if (swc != 0.0f) atomicAdd(&g.histF[t * 2 + 0], swc);   // RED.F32
        if (swu != 0.0f) atomicAdd(&g.histF[t * 2 + 1], swu);
    }
    __threadfence();
    __syncthreads();

    // ---------------- finalize (last block) ----------------
    if (t == 0) {
        unsigned tk = atomicAdd(&g.ticket, 1u);
        if (tk == NB2 - 1) {
            __threadfence();
            float h[88];
            #pragma unroll 4
            for (int i2 = 0; i2 < 88; i2++) h[i2] = g.histF[i2];
            float totAU = 0.0f, totIU = 0.0f;
            #pragma unroll
            for (int b = 0; b < 22; b++) { totAU += h[4*b+3]; totIU += h[4*b+1]; }
            float pAC = 0.0f, pIC = 0.0f, pAU = 0.0f, pIU = 0.0f;
            float auc = 0.0f, prev = 0.0f, prev_tl = 0.0f;
            #pragma unroll 1
            for (int j = 0; j < 21; j++) {
                pAC += h[4*j+2];
                pIC += h[4*j+0];
                pAU += h[4*j+3];
                pIU += h[4*j+1];
                float nau = totAU - pAU, niu = totIU - pIU;
                float avu = (pAC + niu) / (pAC + nau + pIC + niu + 1e-10f);
                float tl  = (j == 20) ? 1.0f : 0.05f * (float)j;
                if (j > 0) auc += (avu + prev) * 0.5f * (tl - prev_tl);
                prev = avu; prev_tl = tl;
            }
            double dn = 1.0 / (double)n;
            out[0] = -logf(fmaxf(auc, 1e-10f)) + (float)(g.fo * dn);
            out[1] = (float)(g.ce * dn);
            // self-reset for next graph replay
            g.ce = 0.0; g.fo = 0.0;
            g.umaxb = 0u; g.uminneg = 0u;
            #pragma unroll 4
            for (int i2 = 0; i2 < 88; i2++) g.histF[i2] = 0.0f;
            g.arrive = 0u; g.workA = 0u;
            __threadfence();
            g.ticket = 0u;
        }
    }
}

// ---------------- launcher --------------------------------------------------
extern "C" void kernel_launch(void* const* d_in, const int* in_sizes, int n_in,
                              void* d_out, int out_size) {
    const float* in0 = (const float*)d_in[0];
    const float* in1 = (const float*)d_in[1];
    int n = in_sizes[0] / CN;
    if (n > NMAX) n = NMAX;

    cudaFuncSetAttribute(fused, cudaFuncAttributeMaxDynamicSharedMemorySize, SMEM_TOTAL);
    fused<<<NB2, T1, SMEM_TOTAL>>>(in0, in1, n, (float*)d_out);
}